// round 13
// baseline (speedup 1.0000x reference)
#include <cuda_runtime.h>
#include <cuda_bf16.h>
#include <cstdint>

#define NROWS 65536
#define DDATA 512
#define DLAT  64
#define KC    64
#define TILE  128
#define NT    256
#define NBLK  (NROWS / TILE)     // 512
#define NITER 10
#define EPSV  1e-8f
#define ALPHA 0.001f

#define XSTR 144
#define CSTR 144
#define RSTR 272

// smem byte offsets (RH aliases CH+CL region -- C dead after phase-1 MMAs)
#define OFF_XH  0                // [128][72] bf16
#define OFF_XL  18432
#define OFF_CH  36864            // [64][72] bf16
#define OFF_CL  46080
#define OFF_RH  36864            // alias: [64 clusters][136 rows] bf16
#define OFF_RL  55296            // [64 clusters][136 rows] bf16
#define OFF_X2  72704
#define OFF_C2  73216
#define OFF_RED 73472
#define SMEM_SZ 73536            // x3 CTAs = 220.6 KB

struct AccBuf { float acc[KC * DLAT]; float cs[KC]; };
__device__ AccBuf g_acc[3];
struct LossBuf { float loss; float pad; double dloss; };
__device__ LossBuf g_l;
__device__ __nv_bfloat16 g_xh[NROWS * DLAT];
__device__ __nv_bfloat16 g_xl[NROWS * DLAT];
__device__ float g_x2[NROWS];

// ---------------- helpers ----------------
__device__ __forceinline__ uint32_t smem_u32(const void* p) {
    uint32_t a;
    asm("{ .reg .u64 t; cvta.to.shared.u64 t, %1; cvt.u32.u64 %0, t; }"
        : "=r"(a) : "l"(p));
    return a;
}
__device__ __forceinline__ void ldm4(uint32_t* r, uint32_t a) {
    asm volatile("ldmatrix.sync.aligned.m8n8.x4.shared.b16 {%0,%1,%2,%3}, [%4];"
        : "=r"(r[0]), "=r"(r[1]), "=r"(r[2]), "=r"(r[3]) : "r"(a));
}
__device__ __forceinline__ void ldm4t(uint32_t* r, uint32_t a) {
    asm volatile("ldmatrix.sync.aligned.m8n8.x4.trans.shared.b16 {%0,%1,%2,%3}, [%4];"
        : "=r"(r[0]), "=r"(r[1]), "=r"(r[2]), "=r"(r[3]) : "r"(a));
}
__device__ __forceinline__ void mma16816(float* d, const uint32_t* a, const uint32_t* b) {
    asm volatile("mma.sync.aligned.m16n8k16.row.col.f32.bf16.bf16.f32 "
        "{%0,%1,%2,%3}, {%4,%5,%6,%7}, {%8,%9}, {%0,%1,%2,%3};"
        : "+f"(d[0]), "+f"(d[1]), "+f"(d[2]), "+f"(d[3])
        : "r"(a[0]), "r"(a[1]), "r"(a[2]), "r"(a[3]), "r"(b[0]), "r"(b[1]));
}
__device__ __forceinline__ void red2(float* p, float a, float b) {
    asm volatile("red.global.add.v2.f32 [%0], {%1,%2};"
                 :: "l"(p), "f"(a), "f"(b) : "memory");
}
__device__ __forceinline__ void split2(float v, uint16_t& h, uint16_t& l) {
    __nv_bfloat16 hb = __float2bfloat16(v);
    __nv_bfloat16 lb = __float2bfloat16(v - __bfloat162float(hb));
    h = __bfloat16_as_ushort(hb);
    l = __bfloat16_as_ushort(lb);
}
__device__ __forceinline__ float sq4(float4 a, float4 b, float s) {
    float d0 = a.x - b.x, d1 = a.y - b.y, d2 = a.z - b.z, d3 = a.w - b.w;
    return fmaf(d0, d0, fmaf(d1, d1, fmaf(d2, d2, fmaf(d3, d3, s))));
}

// ---------------------------------------------------------------------------
// precompute: enc -> bf16 hi/lo split + x2; zero acc[0] + loss
// ---------------------------------------------------------------------------
__global__ void precompute_kernel(const float* __restrict__ enc) {
    int c = blockIdx.x * 256 + threadIdx.x;
    const float4* src = (const float4*)enc + (size_t)c * 4;
    float x2p = 0.f;
    uint32_t hh[8], ll[8];
    #pragma unroll
    for (int q = 0; q < 4; ++q) {
        float4 v = src[q];
        x2p = fmaf(v.x, v.x, fmaf(v.y, v.y, fmaf(v.z, v.z, fmaf(v.w, v.w, x2p))));
        uint16_t h0, l0, h1, l1, h2, l2, h3, l3;
        split2(v.x, h0, l0); split2(v.y, h1, l1);
        split2(v.z, h2, l2); split2(v.w, h3, l3);
        hh[2 * q]     = ((uint32_t)h1 << 16) | h0;
        hh[2 * q + 1] = ((uint32_t)h3 << 16) | h2;
        ll[2 * q]     = ((uint32_t)l1 << 16) | l0;
        ll[2 * q + 1] = ((uint32_t)l3 << 16) | l2;
    }
    uint4* dh = (uint4*)g_xh + (size_t)c * 2;
    uint4* dl = (uint4*)g_xl + (size_t)c * 2;
    dh[0] = make_uint4(hh[0], hh[1], hh[2], hh[3]);
    dh[1] = make_uint4(hh[4], hh[5], hh[6], hh[7]);
    dl[0] = make_uint4(ll[0], ll[1], ll[2], ll[3]);
    dl[1] = make_uint4(ll[4], ll[5], ll[6], ll[7]);

    x2p += __shfl_xor_sync(0xffffffffu, x2p, 1);
    x2p += __shfl_xor_sync(0xffffffffu, x2p, 2);
    if ((c & 3) == 0) g_x2[c >> 2] = x2p;

    if (blockIdx.x < 17) {
        int gid = blockIdx.x * 256 + threadIdx.x;
        if (gid < KC * DLAT) g_acc[0].acc[gid] = 0.f;
        if (gid < KC) g_acc[0].cs[gid] = 0.f;
        if (gid == 0) { g_l.loss = 0.f; g_l.dloss = 0.0; }
    }
}

// ---------------------------------------------------------------------------
// decoder loss: parallel stream, streaming loads (keeps enc split in L2)
// ---------------------------------------------------------------------------
__global__ void decoder_kernel(const float4* __restrict__ X,
                               const float4* __restrict__ Dc, int n4) {
    float ds = 0.f;
    const int stride = gridDim.x * blockDim.x;
    int i = blockIdx.x * blockDim.x + threadIdx.x;
    for (; i + 3 * stride < n4; i += 4 * stride) {
        float4 x0 = __ldcs(X + i),              d0 = __ldcs(Dc + i);
        float4 x1 = __ldcs(X + i + stride),     d1 = __ldcs(Dc + i + stride);
        float4 x2 = __ldcs(X + i + 2 * stride), d2 = __ldcs(Dc + i + 2 * stride);
        float4 x3 = __ldcs(X + i + 3 * stride), d3 = __ldcs(Dc + i + 3 * stride);
        ds = sq4(x0, d0, ds); ds = sq4(x1, d1, ds);
        ds = sq4(x2, d2, ds); ds = sq4(x3, d3, ds);
    }
    for (; i < n4; i += stride) {
        float4 x0 = __ldcs(X + i), d0 = __ldcs(Dc + i);
        ds = sq4(x0, d0, ds);
    }
    __shared__ float rs[8];
    #pragma unroll
    for (int o = 16; o; o >>= 1) ds += __shfl_xor_sync(0xffffffffu, ds, o);
    if ((threadIdx.x & 31) == 0) rs[threadIdx.x >> 5] = ds;
    __syncthreads();
    if (threadIdx.x == 0) {
        double s = 0.0;
        #pragma unroll
        for (int w = 0; w < 8; w++) s += (double)rs[w];
        atomicAdd(&g_l.dloss, s);
    }
}

// ---------------------------------------------------------------------------
// Fused k-means iteration: HMMA, x4 ldmatrix B operands, r hi/lo split
// ---------------------------------------------------------------------------
template<bool FROM_ENC, bool DO_LOSS, bool DO_P2>
__global__ __launch_bounds__(NT, 3) void kmeans_iter(
    const float* __restrict__ enc, int rd, int wr, int zr)
{
    extern __shared__ __align__(128) char smem[];
    const uint32_t sb = smem_u32(smem);
    const int t = threadIdx.x, b = blockIdx.x;
    const int wid = t >> 5, lane = t & 31;
    float* x2_s  = (float*)(smem + OFF_X2);
    float* c2_s  = (float*)(smem + OFF_C2);
    float* red_s = (float*)(smem + OFF_RED);

    if (DO_P2) {
        int gid = b * NT + t;
        if (gid < KC * DLAT) g_acc[zr].acc[gid] = 0.f;
        if (gid < KC) g_acc[zr].cs[gid] = 0.f;
    }

    // ---- x tile: copy precomputed bf16 hi/lo (16B chunks, L2-resident)
    {
        const uint4* gh = (const uint4*)(g_xh + (size_t)(b * TILE) * DLAT);
        const uint4* gl = (const uint4*)(g_xl + (size_t)(b * TILE) * DLAT);
        #pragma unroll
        for (int u = 0; u < 4; ++u) {
            int c = t + u * NT;
            uint32_t a = (uint32_t)((c >> 3) * XSTR + (c & 7) * 16);
            *(uint4*)(smem + OFF_XH + a) = gh[c];
            *(uint4*)(smem + OFF_XL + a) = gl[c];
        }
        if (t < TILE) x2_s[t] = g_x2[b * TILE + t];
    }

    // ---- C tile -> bf16 hi/lo + c2
    {
        int k = t >> 2, jq = t & 3;
        float inv = 1.f;
        const float* srcC;
        if (FROM_ENC) srcC = &enc[k * DLAT];
        else { inv = 1.0f / (g_acc[rd].cs[k] + EPSV); srcC = &g_acc[rd].acc[k * DLAT]; }
        char* ch = smem + OFF_CH + k * CSTR;
        char* cl = smem + OFF_CL + k * CSTR;
        float c2p = 0.f;
        #pragma unroll
        for (int q = 0; q < 4; ++q) {
            int j = jq * 16 + q * 4;
            float4 v = *(const float4*)&srcC[j];
            v.x *= inv; v.y *= inv; v.z *= inv; v.w *= inv;
            c2p = fmaf(v.x, v.x, fmaf(v.y, v.y, fmaf(v.z, v.z, fmaf(v.w, v.w, c2p))));
            uint16_t h0, l0, h1, l1, h2, l2, h3, l3;
            split2(v.x, h0, l0); split2(v.y, h1, l1);
            split2(v.z, h2, l2); split2(v.w, h3, l3);
            *(uint32_t*)(ch + j * 2)     = ((uint32_t)h1 << 16) | h0;
            *(uint32_t*)(ch + j * 2 + 4) = ((uint32_t)h3 << 16) | h2;
            *(uint32_t*)(cl + j * 2)     = ((uint32_t)l1 << 16) | l0;
            *(uint32_t*)(cl + j * 2 + 4) = ((uint32_t)l3 << 16) | l2;
        }
        c2p += __shfl_xor_sync(0xffffffffu, c2p, 1);
        c2p += __shfl_xor_sync(0xffffffffu, c2p, 2);
        if (jq == 0) c2_s[k] = c2p;
    }
    __syncthreads();                                   // S1

    const int g = lane >> 3, ri = lane & 7;
    // x4 non-trans: row = (lane&7)+((lane>>4)<<3), k-byte = ((lane>>3)&1)*16
    const uint32_t b4row = (uint32_t)((lane & 7) + ((lane >> 4) << 3));
    const uint32_t b4k   = (uint32_t)(((lane >> 3) & 1) << 4);
    // x4 trans: row = ((lane>>3)&1)*8+(lane&7), col-byte = ((lane>>4)&1)*16
    const uint32_t t4row = (uint32_t)((((lane >> 3) & 1) << 3) + (lane & 7));
    const uint32_t t4col = (uint32_t)(((lane >> 4) & 1) << 4);

    // ======== phase 1: D[row][cluster] = x . c (3-term bf16 split) ========
    float D[8][4];
    #pragma unroll
    for (int nt = 0; nt < 8; ++nt)
        #pragma unroll
        for (int i = 0; i < 4; ++i) D[nt][i] = 0.f;
    {
        const int wm = wid * 16;
        uint32_t aH = sb + OFF_XH + (uint32_t)(wm + (g & 1) * 8 + ri) * XSTR
                    + (uint32_t)((g >> 1) * 16);
        uint32_t aL = aH + (OFF_XL - OFF_XH);
        uint32_t bH = sb + OFF_CH + b4row * CSTR + b4k;
        uint32_t bL = bH + (OFF_CL - OFF_CH);
        #pragma unroll
        for (int ks = 0; ks < 4; ++ks) {
            uint32_t ah[4], al[4];
            ldm4(ah, aH + ks * 32);
            ldm4(al, aL + ks * 32);
            #pragma unroll
            for (int p = 0; p < 4; ++p) {        // cluster pair p: nt=2p,2p+1
                uint32_t bh4[4], bl4[4];
                ldm4(bh4, bH + p * (16 * CSTR) + ks * 32);
                ldm4(bl4, bL + p * (16 * CSTR) + ks * 32);
                mma16816(D[2 * p],     ah, bh4 + 0);
                mma16816(D[2 * p],     al, bh4 + 0);
                mma16816(D[2 * p],     ah, bl4 + 0);
                mma16816(D[2 * p + 1], ah, bh4 + 2);
                mma16816(D[2 * p + 1], al, bh4 + 2);
                mma16816(D[2 * p + 1], ah, bl4 + 2);
            }
        }
    }

    // ======== epilogue 1a: d2 + softmax in registers ========
    const int wm = wid * 16;
    const int qr = lane >> 2, qc = lane & 3;
    const int r0 = wm + qr, r1 = r0 + 8;
    float iZ0, iZ1;
    {
        const float x20 = x2_s[r0], x21 = x2_s[r1];
        float mn0 = 1e30f, mn1 = 1e30f;
        #pragma unroll
        for (int nt = 0; nt < 8; ++nt) {
            int c0 = nt * 8 + 2 * qc;
            float ca = c2_s[c0], cb = c2_s[c0 + 1];
            float d00 = fmaxf(x20 + ca - 2.f * D[nt][0], 0.f);
            float d01 = fmaxf(x20 + cb - 2.f * D[nt][1], 0.f);
            float d10 = fmaxf(x21 + ca - 2.f * D[nt][2], 0.f);
            float d11 = fmaxf(x21 + cb - 2.f * D[nt][3], 0.f);
            D[nt][0] = d00; D[nt][1] = d01; D[nt][2] = d10; D[nt][3] = d11;
            mn0 = fminf(mn0, fminf(d00, d01));
            mn1 = fminf(mn1, fminf(d10, d11));
        }
        mn0 = fminf(mn0, __shfl_xor_sync(0xffffffffu, mn0, 1));
        mn0 = fminf(mn0, __shfl_xor_sync(0xffffffffu, mn0, 2));
        mn1 = fminf(mn1, __shfl_xor_sync(0xffffffffu, mn1, 1));
        mn1 = fminf(mn1, __shfl_xor_sync(0xffffffffu, mn1, 2));
        float Z0 = 0.f, Z1 = 0.f, ln0 = 0.f, ln1 = 0.f;
        #pragma unroll
        for (int nt = 0; nt < 8; ++nt) {
            float e00 = __expf(mn0 - D[nt][0]);
            float e01 = __expf(mn0 - D[nt][1]);
            float e10 = __expf(mn1 - D[nt][2]);
            float e11 = __expf(mn1 - D[nt][3]);
            if (DO_LOSS) {
                ln0 = fmaf(e00, D[nt][0], fmaf(e01, D[nt][1], ln0));
                ln1 = fmaf(e10, D[nt][2], fmaf(e11, D[nt][3], ln1));
            }
            Z0 += e00 + e01; Z1 += e10 + e11;
            D[nt][0] = e00; D[nt][1] = e01; D[nt][2] = e10; D[nt][3] = e11;
        }
        Z0 += __shfl_xor_sync(0xffffffffu, Z0, 1);
        Z0 += __shfl_xor_sync(0xffffffffu, Z0, 2);
        Z1 += __shfl_xor_sync(0xffffffffu, Z1, 1);
        Z1 += __shfl_xor_sync(0xffffffffu, Z1, 2);
        iZ0 = 1.0f / Z0; iZ1 = 1.0f / Z1;
        if (DO_LOSS) {
            ln0 += __shfl_xor_sync(0xffffffffu, ln0, 1);
            ln0 += __shfl_xor_sync(0xffffffffu, ln0, 2);
            ln1 += __shfl_xor_sync(0xffffffffu, ln1, 1);
            ln1 += __shfl_xor_sync(0xffffffffu, ln1, 2);
            float lrow = (ln0 * iZ0 + ln1 * iZ1) * 0.25f;
            #pragma unroll
            for (int o = 16; o; o >>= 1) lrow += __shfl_xor_sync(0xffffffffu, lrow, o);
            if (lane == 0) red_s[wid] = lrow;
        }
    }
    __syncthreads();                                   // S_mid (C reads done)

    if (DO_LOSS && t == 0) {
        float s = 0.f;
        #pragma unroll
        for (int w = 0; w < 8; w++) s += red_s[w];
        atomicAdd(&g_l.loss, s);
    }
    if (!DO_P2) return;

    // ======== epilogue 1b: r stores (hi/lo split) + colsum ========
    {
        #pragma unroll
        for (int nt = 0; nt < 8; ++nt) {
            int c0 = nt * 8 + 2 * qc;
            float r00 = D[nt][0] * iZ0, r01 = D[nt][1] * iZ0;
            float r10 = D[nt][2] * iZ1, r11 = D[nt][3] * iZ1;
            uint16_t h, l;
            char* pH0 = smem + OFF_RH + c0 * RSTR;
            char* pL0 = smem + OFF_RL + c0 * RSTR;
            split2(r00, h, l);
            *(uint16_t*)(pH0 + r0 * 2) = h; *(uint16_t*)(pL0 + r0 * 2) = l;
            split2(r10, h, l);
            *(uint16_t*)(pH0 + r1 * 2) = h; *(uint16_t*)(pL0 + r1 * 2) = l;
            split2(r01, h, l);
            *(uint16_t*)(pH0 + RSTR + r0 * 2) = h; *(uint16_t*)(pL0 + RSTR + r0 * 2) = l;
            split2(r11, h, l);
            *(uint16_t*)(pH0 + RSTR + r1 * 2) = h; *(uint16_t*)(pL0 + RSTR + r1 * 2) = l;
            float cs0 = r00 + r10, cs1 = r01 + r11;
            cs0 += __shfl_xor_sync(0xffffffffu, cs0, 4);
            cs0 += __shfl_xor_sync(0xffffffffu, cs0, 8);
            cs0 += __shfl_xor_sync(0xffffffffu, cs0, 16);
            cs1 += __shfl_xor_sync(0xffffffffu, cs1, 4);
            cs1 += __shfl_xor_sync(0xffffffffu, cs1, 8);
            cs1 += __shfl_xor_sync(0xffffffffu, cs1, 16);
            if (qr == 0) red2(&g_acc[wr].cs[c0], cs0, cs1);
        }
    }
    __syncthreads();                                   // S2

    // ======== phase 2: Cacc[k][j] += sum_rows r[row][k] x[row][j] ========
    float E[4][4];
    #pragma unroll
    for (int nt = 0; nt < 4; ++nt)
        #pragma unroll
        for (int i = 0; i < 4; ++i) E[nt][i] = 0.f;
    const int cm = (wid & 3) * 16, jn = (wid >> 2) * 32;
    {
        uint32_t aH = sb + OFF_RH + (uint32_t)(cm + (g & 1) * 8 + ri) * RSTR
                    + (uint32_t)((g >> 1) * 16);
        uint32_t aL = sb + OFF_RL + (uint32_t)(cm + (g & 1) * 8 + ri) * RSTR
                    + (uint32_t)((g >> 1) * 16);
        uint32_t bH = sb + OFF_XH + t4row * XSTR + t4col + (uint32_t)(jn * 2);
        uint32_t bL = bH + (OFF_XL - OFF_XH);
        #pragma unroll
        for (int ks = 0; ks < 8; ++ks) {
            uint32_t ah[4], al[4];
            ldm4(ah, aH + ks * 32);
            ldm4(al, aL + ks * 32);
            #pragma unroll
            for (int p = 0; p < 2; ++p) {        // j pair p: nt=2p,2p+1
                uint32_t bh4[4], bl4[4];
                ldm4t(bh4, bH + ks * (16 * XSTR) + p * 32);
                ldm4t(bl4, bL + ks * (16 * XSTR) + p * 32);
                mma16816(E[2 * p],     ah, bh4 + 0);
                mma16816(E[2 * p],     al, bh4 + 0);
                mma16816(E[2 * p],     ah, bl4 + 0);
                mma16816(E[2 * p + 1], ah, bh4 + 2);
                mma16816(E[2 * p + 1], al, bh4 + 2);
                mma16816(E[2 * p + 1], ah, bl4 + 2);
            }
        }
    }
    {
        float* acc = g_acc[wr].acc;
        #pragma unroll
        for (int nt = 0; nt < 4; ++nt) {
            int j = jn + nt * 8 + 2 * qc;
            red2(&acc[(cm + qr) * DLAT + j], E[nt][0], E[nt][1]);
            red2(&acc[(cm + qr + 8) * DLAT + j], E[nt][2], E[nt][3]);
        }
    }
}

__global__ void final_kernel(float* out) {
    out[0] = (float)(g_l.dloss * (1.0 / ((double)NROWS * (double)DDATA)))
           + ALPHA * (g_l.loss / (float)NROWS);
}

// ---------------------------------------------------------------------------
extern "C" void kernel_launch(void* const* d_in, const int* in_sizes, int n_in,
                              void* d_out, int out_size) {
    const float* X   = (const float*)d_in[0];
    const float* enc = (const float*)d_in[1];
    const float* dec = (const float*)d_in[2];
    float* out = (float*)d_out;
    const float4* X4 = (const float4*)X;
    const float4* D4 = (const float4*)dec;

    static cudaStream_t s2;
    static cudaEvent_t evFork, evJoin;
    static bool inited = false;
    if (!inited) {
        cudaStreamCreateWithFlags(&s2, cudaStreamNonBlocking);
        cudaEventCreateWithFlags(&evFork, cudaEventDisableTiming);
        cudaEventCreateWithFlags(&evJoin, cudaEventDisableTiming);
        inited = true;
    }

    cudaFuncSetAttribute(kmeans_iter<true,  false, true >,
                         cudaFuncAttributeMaxDynamicSharedMemorySize, SMEM_SZ);
    cudaFuncSetAttribute(kmeans_iter<false, false, true >,
                         cudaFuncAttributeMaxDynamicSharedMemorySize, SMEM_SZ);
    cudaFuncSetAttribute(kmeans_iter<false, true,  false>,
                         cudaFuncAttributeMaxDynamicSharedMemorySize, SMEM_SZ);

    const int N4 = NROWS * DDATA / 4;

    precompute_kernel<<<1024, 256>>>(enc);

    // fork: decoder loss runs concurrently with the k-means chain
    cudaEventRecord(evFork, 0);
    cudaStreamWaitEvent(s2, evFork, 0);
    decoder_kernel<<<1184, 256, 0, s2>>>(X4, D4, N4);
    cudaEventRecord(evJoin, s2);

    // iter 0: C from enc; writes buf0 (pre-zeroed), zeroes buf1
    kmeans_iter<true, false, true><<<NBLK, NT, SMEM_SZ>>>(enc, 0, 0, 1);
    for (int it = 1; it <= 8; ++it)
        kmeans_iter<false, false, true><<<NBLK, NT, SMEM_SZ>>>(
            enc, (it - 1) % 3, it % 3, (it + 1) % 3);
    // iter 9: loss only
    kmeans_iter<false, true, false><<<NBLK, NT, SMEM_SZ>>>(enc, 2, 0, 0);

    // join
    cudaStreamWaitEvent(0, evJoin, 0);
    final_kernel<<<1, 1>>>(out);
}

// round 14
// speedup vs baseline: 1.0995x; 1.0995x over previous
#include <cuda_runtime.h>
#include <cuda_bf16.h>
#include <cstdint>

#define NROWS 65536
#define DDATA 512
#define DLAT  64
#define KC    64
#define TILE  128
#define NT    256
#define NBLK  256                // CTAs; each handles 2 tiles (512 tiles total)
#define NITER 10
#define EPSV  1e-8f
#define ALPHA 0.001f

#define XSTR 144
#define CSTR 144
#define RSTR 272

// smem byte offsets (NO aliasing: C survives across the 2-tile loop)
#define OFF_XH  0                // [128][72] bf16
#define OFF_XL  18432
#define OFF_CH  36864            // [64][72] bf16
#define OFF_CL  46080
#define OFF_RH  55296            // [64 clusters][136 rows] bf16
#define OFF_RL  72704
#define OFF_X2  90112            // [128] f32
#define OFF_C2  90624            // [64] f32
#define OFF_RED 90880            // [8] f32
#define SMEM_SZ 90912            // x2 CTAs = 181.8 KB <= 228 KB

struct AccBuf { float acc[KC * DLAT]; float cs[KC]; };
__device__ AccBuf g_acc[3];
struct LossBuf { float loss; float pad; double dloss; };
__device__ LossBuf g_l;
__device__ __nv_bfloat16 g_xh[NROWS * DLAT];
__device__ __nv_bfloat16 g_xl[NROWS * DLAT];
__device__ float g_x2[NROWS];

// ---------------- helpers ----------------
__device__ __forceinline__ uint32_t smem_u32(const void* p) {
    uint32_t a;
    asm("{ .reg .u64 t; cvta.to.shared.u64 t, %1; cvt.u32.u64 %0, t; }"
        : "=r"(a) : "l"(p));
    return a;
}
__device__ __forceinline__ void ldm4(uint32_t* r, uint32_t a) {
    asm volatile("ldmatrix.sync.aligned.m8n8.x4.shared.b16 {%0,%1,%2,%3}, [%4];"
        : "=r"(r[0]), "=r"(r[1]), "=r"(r[2]), "=r"(r[3]) : "r"(a));
}
__device__ __forceinline__ void ldm4t(uint32_t* r, uint32_t a) {
    asm volatile("ldmatrix.sync.aligned.m8n8.x4.trans.shared.b16 {%0,%1,%2,%3}, [%4];"
        : "=r"(r[0]), "=r"(r[1]), "=r"(r[2]), "=r"(r[3]) : "r"(a));
}
__device__ __forceinline__ void mma16816(float* d, const uint32_t* a, const uint32_t* b) {
    asm volatile("mma.sync.aligned.m16n8k16.row.col.f32.bf16.bf16.f32 "
        "{%0,%1,%2,%3}, {%4,%5,%6,%7}, {%8,%9}, {%0,%1,%2,%3};"
        : "+f"(d[0]), "+f"(d[1]), "+f"(d[2]), "+f"(d[3])
        : "r"(a[0]), "r"(a[1]), "r"(a[2]), "r"(a[3]), "r"(b[0]), "r"(b[1]));
}
__device__ __forceinline__ void red2(float* p, float a, float b) {
    asm volatile("red.global.add.v2.f32 [%0], {%1,%2};"
                 :: "l"(p), "f"(a), "f"(b) : "memory");
}
__device__ __forceinline__ void split2(float v, uint16_t& h, uint16_t& l) {
    __nv_bfloat16 hb = __float2bfloat16(v);
    __nv_bfloat16 lb = __float2bfloat16(v - __bfloat162float(hb));
    h = __bfloat16_as_ushort(hb);
    l = __bfloat16_as_ushort(lb);
}
__device__ __forceinline__ float sq4(float4 a, float4 b, float s) {
    float d0 = a.x - b.x, d1 = a.y - b.y, d2 = a.z - b.z, d3 = a.w - b.w;
    return fmaf(d0, d0, fmaf(d1, d1, fmaf(d2, d2, fmaf(d3, d3, s))));
}

// ---------------------------------------------------------------------------
// precompute: enc -> bf16 hi/lo split + x2; zero acc[0] + loss
// ---------------------------------------------------------------------------
__global__ void precompute_kernel(const float* __restrict__ enc) {
    int c = blockIdx.x * 256 + threadIdx.x;
    const float4* src = (const float4*)enc + (size_t)c * 4;
    float x2p = 0.f;
    uint32_t hh[8], ll[8];
    #pragma unroll
    for (int q = 0; q < 4; ++q) {
        float4 v = src[q];
        x2p = fmaf(v.x, v.x, fmaf(v.y, v.y, fmaf(v.z, v.z, fmaf(v.w, v.w, x2p))));
        uint16_t h0, l0, h1, l1, h2, l2, h3, l3;
        split2(v.x, h0, l0); split2(v.y, h1, l1);
        split2(v.z, h2, l2); split2(v.w, h3, l3);
        hh[2 * q]     = ((uint32_t)h1 << 16) | h0;
        hh[2 * q + 1] = ((uint32_t)h3 << 16) | h2;
        ll[2 * q]     = ((uint32_t)l1 << 16) | l0;
        ll[2 * q + 1] = ((uint32_t)l3 << 16) | l2;
    }
    uint4* dh = (uint4*)g_xh + (size_t)c * 2;
    uint4* dl = (uint4*)g_xl + (size_t)c * 2;
    dh[0] = make_uint4(hh[0], hh[1], hh[2], hh[3]);
    dh[1] = make_uint4(hh[4], hh[5], hh[6], hh[7]);
    dl[0] = make_uint4(ll[0], ll[1], ll[2], ll[3]);
    dl[1] = make_uint4(ll[4], ll[5], ll[6], ll[7]);

    x2p += __shfl_xor_sync(0xffffffffu, x2p, 1);
    x2p += __shfl_xor_sync(0xffffffffu, x2p, 2);
    if ((c & 3) == 0) g_x2[c >> 2] = x2p;

    if (blockIdx.x < 17) {
        int gid = blockIdx.x * 256 + threadIdx.x;
        if (gid < KC * DLAT) g_acc[0].acc[gid] = 0.f;
        if (gid < KC) g_acc[0].cs[gid] = 0.f;
        if (gid == 0) { g_l.loss = 0.f; g_l.dloss = 0.0; }
    }
}

// ---------------------------------------------------------------------------
// decoder loss: parallel stream, streaming loads (keeps enc split in L2)
// ---------------------------------------------------------------------------
__global__ void decoder_kernel(const float4* __restrict__ X,
                               const float4* __restrict__ Dc, int n4) {
    float ds = 0.f;
    const int stride = gridDim.x * blockDim.x;
    int i = blockIdx.x * blockDim.x + threadIdx.x;
    for (; i + 3 * stride < n4; i += 4 * stride) {
        float4 x0 = __ldcs(X + i),              d0 = __ldcs(Dc + i);
        float4 x1 = __ldcs(X + i + stride),     d1 = __ldcs(Dc + i + stride);
        float4 x2 = __ldcs(X + i + 2 * stride), d2 = __ldcs(Dc + i + 2 * stride);
        float4 x3 = __ldcs(X + i + 3 * stride), d3 = __ldcs(Dc + i + 3 * stride);
        ds = sq4(x0, d0, ds); ds = sq4(x1, d1, ds);
        ds = sq4(x2, d2, ds); ds = sq4(x3, d3, ds);
    }
    for (; i < n4; i += stride) {
        float4 x0 = __ldcs(X + i), d0 = __ldcs(Dc + i);
        ds = sq4(x0, d0, ds);
    }
    __shared__ float rs[8];
    #pragma unroll
    for (int o = 16; o; o >>= 1) ds += __shfl_xor_sync(0xffffffffu, ds, o);
    if ((threadIdx.x & 31) == 0) rs[threadIdx.x >> 5] = ds;
    __syncthreads();
    if (threadIdx.x == 0) {
        double s = 0.0;
        #pragma unroll
        for (int w = 0; w < 8; w++) s += (double)rs[w];
        atomicAdd(&g_l.dloss, s);
    }
}

// ---------------------------------------------------------------------------
// Fused k-means iteration: 2 tiles per CTA, single wave, C built once
// ---------------------------------------------------------------------------
template<bool FROM_ENC, bool DO_LOSS, bool DO_P2>
__global__ __launch_bounds__(NT, 2) void kmeans_iter(
    const float* __restrict__ enc, int rd, int wr, int zr)
{
    extern __shared__ __align__(128) char smem[];
    const uint32_t sb = smem_u32(smem);
    const int t = threadIdx.x, b = blockIdx.x;
    const int wid = t >> 5, lane = t & 31;
    float* x2_s  = (float*)(smem + OFF_X2);
    float* c2_s  = (float*)(smem + OFF_C2);
    float* red_s = (float*)(smem + OFF_RED);

    if (DO_P2) {
        int gid = b * NT + t;
        if (gid < KC * DLAT) g_acc[zr].acc[gid] = 0.f;
        if (gid < KC) g_acc[zr].cs[gid] = 0.f;
    }

    // ---- C tile -> bf16 hi/lo + c2 (ONCE per CTA)
    {
        int k = t >> 2, jq = t & 3;
        float inv = 1.f;
        const float* srcC;
        if (FROM_ENC) srcC = &enc[k * DLAT];
        else { inv = 1.0f / (g_acc[rd].cs[k] + EPSV); srcC = &g_acc[rd].acc[k * DLAT]; }
        char* ch = smem + OFF_CH + k * CSTR;
        char* cl = smem + OFF_CL + k * CSTR;
        float c2p = 0.f;
        #pragma unroll
        for (int q = 0; q < 4; ++q) {
            int j = jq * 16 + q * 4;
            float4 v = *(const float4*)&srcC[j];
            v.x *= inv; v.y *= inv; v.z *= inv; v.w *= inv;
            c2p = fmaf(v.x, v.x, fmaf(v.y, v.y, fmaf(v.z, v.z, fmaf(v.w, v.w, c2p))));
            uint16_t h0, l0, h1, l1, h2, l2, h3, l3;
            split2(v.x, h0, l0); split2(v.y, h1, l1);
            split2(v.z, h2, l2); split2(v.w, h3, l3);
            *(uint32_t*)(ch + j * 2)     = ((uint32_t)h1 << 16) | h0;
            *(uint32_t*)(ch + j * 2 + 4) = ((uint32_t)h3 << 16) | h2;
            *(uint32_t*)(cl + j * 2)     = ((uint32_t)l1 << 16) | l0;
            *(uint32_t*)(cl + j * 2 + 4) = ((uint32_t)l3 << 16) | l2;
        }
        c2p += __shfl_xor_sync(0xffffffffu, c2p, 1);
        c2p += __shfl_xor_sync(0xffffffffu, c2p, 2);
        if (jq == 0) c2_s[k] = c2p;
    }

    const int g = lane >> 3, ri = lane & 7;
    const uint32_t b4row = (uint32_t)((lane & 7) + ((lane >> 4) << 3));
    const uint32_t b4k   = (uint32_t)(((lane >> 3) & 1) << 4);
    const uint32_t t4row = (uint32_t)((((lane >> 3) & 1) << 3) + (lane & 7));
    const uint32_t t4col = (uint32_t)(((lane >> 4) & 1) << 4);
    const int wm = wid * 16;
    const int qr = lane >> 2, qc = lane & 3;

    #pragma unroll 1
    for (int tt = 0; tt < 2; ++tt) {
        const int tile = b + tt * NBLK;

        // ---- x tile: copy precomputed bf16 hi/lo (16B chunks, L2-resident)
        {
            const uint4* gh = (const uint4*)(g_xh + (size_t)(tile * TILE) * DLAT);
            const uint4* gl = (const uint4*)(g_xl + (size_t)(tile * TILE) * DLAT);
            #pragma unroll
            for (int u = 0; u < 4; ++u) {
                int c = t + u * NT;
                uint32_t a = (uint32_t)((c >> 3) * XSTR + (c & 7) * 16);
                *(uint4*)(smem + OFF_XH + a) = gh[c];
                *(uint4*)(smem + OFF_XL + a) = gl[c];
            }
            if (t < TILE) x2_s[t] = g_x2[tile * TILE + t];
        }
        __syncthreads();                               // S1: x (and C, tt=0) ready

        // ======== phase 1: D[row][cluster] = x . c (3-term bf16 split) ====
        float D[8][4];
        #pragma unroll
        for (int nt = 0; nt < 8; ++nt)
            #pragma unroll
            for (int i = 0; i < 4; ++i) D[nt][i] = 0.f;
        {
            uint32_t aH = sb + OFF_XH + (uint32_t)(wm + (g & 1) * 8 + ri) * XSTR
                        + (uint32_t)((g >> 1) * 16);
            uint32_t aL = aH + (OFF_XL - OFF_XH);
            uint32_t bH = sb + OFF_CH + b4row * CSTR + b4k;
            uint32_t bL = bH + (OFF_CL - OFF_CH);
            #pragma unroll
            for (int ks = 0; ks < 4; ++ks) {
                uint32_t ah[4], al[4];
                ldm4(ah, aH + ks * 32);
                ldm4(al, aL + ks * 32);
                #pragma unroll
                for (int p = 0; p < 4; ++p) {
                    uint32_t bh4[4], bl4[4];
                    ldm4(bh4, bH + p * (16 * CSTR) + ks * 32);
                    ldm4(bl4, bL + p * (16 * CSTR) + ks * 32);
                    mma16816(D[2 * p],     ah, bh4 + 0);
                    mma16816(D[2 * p],     al, bh4 + 0);
                    mma16816(D[2 * p],     ah, bl4 + 0);
                    mma16816(D[2 * p + 1], ah, bh4 + 2);
                    mma16816(D[2 * p + 1], al, bh4 + 2);
                    mma16816(D[2 * p + 1], ah, bl4 + 2);
                }
            }
        }

        // ======== epilogue: d2 + softmax in registers ========
        const int r0 = wm + qr, r1 = r0 + 8;
        float iZ0, iZ1;
        {
            const float x20 = x2_s[r0], x21 = x2_s[r1];
            float mn0 = 1e30f, mn1 = 1e30f;
            #pragma unroll
            for (int nt = 0; nt < 8; ++nt) {
                int c0 = nt * 8 + 2 * qc;
                float ca = c2_s[c0], cb = c2_s[c0 + 1];
                float d00 = fmaxf(x20 + ca - 2.f * D[nt][0], 0.f);
                float d01 = fmaxf(x20 + cb - 2.f * D[nt][1], 0.f);
                float d10 = fmaxf(x21 + ca - 2.f * D[nt][2], 0.f);
                float d11 = fmaxf(x21 + cb - 2.f * D[nt][3], 0.f);
                D[nt][0] = d00; D[nt][1] = d01; D[nt][2] = d10; D[nt][3] = d11;
                mn0 = fminf(mn0, fminf(d00, d01));
                mn1 = fminf(mn1, fminf(d10, d11));
            }
            mn0 = fminf(mn0, __shfl_xor_sync(0xffffffffu, mn0, 1));
            mn0 = fminf(mn0, __shfl_xor_sync(0xffffffffu, mn0, 2));
            mn1 = fminf(mn1, __shfl_xor_sync(0xffffffffu, mn1, 1));
            mn1 = fminf(mn1, __shfl_xor_sync(0xffffffffu, mn1, 2));
            float Z0 = 0.f, Z1 = 0.f, ln0 = 0.f, ln1 = 0.f;
            #pragma unroll
            for (int nt = 0; nt < 8; ++nt) {
                float e00 = __expf(mn0 - D[nt][0]);
                float e01 = __expf(mn0 - D[nt][1]);
                float e10 = __expf(mn1 - D[nt][2]);
                float e11 = __expf(mn1 - D[nt][3]);
                if (DO_LOSS) {
                    ln0 = fmaf(e00, D[nt][0], fmaf(e01, D[nt][1], ln0));
                    ln1 = fmaf(e10, D[nt][2], fmaf(e11, D[nt][3], ln1));
                }
                Z0 += e00 + e01; Z1 += e10 + e11;
                D[nt][0] = e00; D[nt][1] = e01; D[nt][2] = e10; D[nt][3] = e11;
            }
            Z0 += __shfl_xor_sync(0xffffffffu, Z0, 1);
            Z0 += __shfl_xor_sync(0xffffffffu, Z0, 2);
            Z1 += __shfl_xor_sync(0xffffffffu, Z1, 1);
            Z1 += __shfl_xor_sync(0xffffffffu, Z1, 2);
            iZ0 = 1.0f / Z0; iZ1 = 1.0f / Z1;
            if (DO_LOSS) {
                ln0 += __shfl_xor_sync(0xffffffffu, ln0, 1);
                ln0 += __shfl_xor_sync(0xffffffffu, ln0, 2);
                ln1 += __shfl_xor_sync(0xffffffffu, ln1, 1);
                ln1 += __shfl_xor_sync(0xffffffffu, ln1, 2);
                float lrow = (ln0 * iZ0 + ln1 * iZ1) * 0.25f;
                #pragma unroll
                for (int o = 16; o; o >>= 1)
                    lrow += __shfl_xor_sync(0xffffffffu, lrow, o);
                if (lane == 0) red_s[wid] = lrow;
            }
        }

        if (!DO_P2) {
            __syncthreads();
            if (DO_LOSS && t == 0) {
                float s = 0.f;
                #pragma unroll
                for (int w = 0; w < 8; w++) s += red_s[w];
                atomicAdd(&g_l.loss, s);
            }
            __syncthreads();                           // red_s reuse next tile
            continue;
        }

        // ======== r stores (hi/lo split) + colsum ========
        {
            #pragma unroll
            for (int nt = 0; nt < 8; ++nt) {
                int c0 = nt * 8 + 2 * qc;
                float r00 = D[nt][0] * iZ0, r01 = D[nt][1] * iZ0;
                float r10 = D[nt][2] * iZ1, r11 = D[nt][3] * iZ1;
                uint16_t h, l;
                char* pH0 = smem + OFF_RH + c0 * RSTR;
                char* pL0 = smem + OFF_RL + c0 * RSTR;
                split2(r00, h, l);
                *(uint16_t*)(pH0 + r0 * 2) = h; *(uint16_t*)(pL0 + r0 * 2) = l;
                split2(r10, h, l);
                *(uint16_t*)(pH0 + r1 * 2) = h; *(uint16_t*)(pL0 + r1 * 2) = l;
                split2(r01, h, l);
                *(uint16_t*)(pH0 + RSTR + r0 * 2) = h;
                *(uint16_t*)(pL0 + RSTR + r0 * 2) = l;
                split2(r11, h, l);
                *(uint16_t*)(pH0 + RSTR + r1 * 2) = h;
                *(uint16_t*)(pL0 + RSTR + r1 * 2) = l;
                float cs0 = r00 + r10, cs1 = r01 + r11;
                cs0 += __shfl_xor_sync(0xffffffffu, cs0, 4);
                cs0 += __shfl_xor_sync(0xffffffffu, cs0, 8);
                cs0 += __shfl_xor_sync(0xffffffffu, cs0, 16);
                cs1 += __shfl_xor_sync(0xffffffffu, cs1, 4);
                cs1 += __shfl_xor_sync(0xffffffffu, cs1, 8);
                cs1 += __shfl_xor_sync(0xffffffffu, cs1, 16);
                if (qr == 0) red2(&g_acc[wr].cs[c0], cs0, cs1);
            }
        }
        __syncthreads();                               // S2: r ready

        // ======== phase 2: Cacc[k][j] += sum_rows r[row][k] x[row][j] ====
        float E[4][4];
        #pragma unroll
        for (int nt = 0; nt < 4; ++nt)
            #pragma unroll
            for (int i = 0; i < 4; ++i) E[nt][i] = 0.f;
        const int cm = (wid & 3) * 16, jn = (wid >> 2) * 32;
        {
            uint32_t aH = sb + OFF_RH + (uint32_t)(cm + (g & 1) * 8 + ri) * RSTR
                        + (uint32_t)((g >> 1) * 16);
            uint32_t aL = sb + OFF_RL + (uint32_t)(cm + (g & 1) * 8 + ri) * RSTR
                        + (uint32_t)((g >> 1) * 16);
            uint32_t bH = sb + OFF_XH + t4row * XSTR + t4col + (uint32_t)(jn * 2);
            uint32_t bL = bH + (OFF_XL - OFF_XH);
            #pragma unroll
            for (int ks = 0; ks < 8; ++ks) {
                uint32_t ah[4], al[4];
                ldm4(ah, aH + ks * 32);
                ldm4(al, aL + ks * 32);
                #pragma unroll
                for (int p = 0; p < 2; ++p) {
                    uint32_t bh4[4], bl4[4];
                    ldm4t(bh4, bH + ks * (16 * XSTR) + p * 32);
                    ldm4t(bl4, bL + ks * (16 * XSTR) + p * 32);
                    mma16816(E[2 * p],     ah, bh4 + 0);
                    mma16816(E[2 * p],     al, bh4 + 0);
                    mma16816(E[2 * p],     ah, bl4 + 0);
                    mma16816(E[2 * p + 1], ah, bh4 + 2);
                    mma16816(E[2 * p + 1], al, bh4 + 2);
                    mma16816(E[2 * p + 1], ah, bl4 + 2);
                }
            }
        }
        {
            float* acc = g_acc[wr].acc;
            #pragma unroll
            for (int nt = 0; nt < 4; ++nt) {
                int j = jn + nt * 8 + 2 * qc;
                red2(&acc[(cm + qr) * DLAT + j], E[nt][0], E[nt][1]);
                red2(&acc[(cm + qr + 8) * DLAT + j], E[nt][2], E[nt][3]);
            }
        }
        __syncthreads();                               // S3: smem reuse next tile
    }
}

__global__ void final_kernel(float* out) {
    out[0] = (float)(g_l.dloss * (1.0 / ((double)NROWS * (double)DDATA)))
           + ALPHA * (g_l.loss / (float)NROWS);
}

// ---------------------------------------------------------------------------
extern "C" void kernel_launch(void* const* d_in, const int* in_sizes, int n_in,
                              void* d_out, int out_size) {
    const float* X   = (const float*)d_in[0];
    const float* enc = (const float*)d_in[1];
    const float* dec = (const float*)d_in[2];
    float* out = (float*)d_out;
    const float4* X4 = (const float4*)X;
    const float4* D4 = (const float4*)dec;

    static cudaStream_t s2;
    static cudaEvent_t evFork, evJoin;
    static bool inited = false;
    if (!inited) {
        cudaStreamCreateWithFlags(&s2, cudaStreamNonBlocking);
        cudaEventCreateWithFlags(&evFork, cudaEventDisableTiming);
        cudaEventCreateWithFlags(&evJoin, cudaEventDisableTiming);
        inited = true;
    }

    cudaFuncSetAttribute(kmeans_iter<true,  false, true >,
                         cudaFuncAttributeMaxDynamicSharedMemorySize, SMEM_SZ);
    cudaFuncSetAttribute(kmeans_iter<false, false, true >,
                         cudaFuncAttributeMaxDynamicSharedMemorySize, SMEM_SZ);
    cudaFuncSetAttribute(kmeans_iter<false, true,  false>,
                         cudaFuncAttributeMaxDynamicSharedMemorySize, SMEM_SZ);

    const int N4 = NROWS * DDATA / 4;

    precompute_kernel<<<1024, 256>>>(enc);

    // fork: decoder loss runs concurrently with the k-means chain
    cudaEventRecord(evFork, 0);
    cudaStreamWaitEvent(s2, evFork, 0);
    decoder_kernel<<<1184, 256, 0, s2>>>(X4, D4, N4);
    cudaEventRecord(evJoin, s2);

    // iter 0: C from enc; writes buf0 (pre-zeroed), zeroes buf1
    kmeans_iter<true, false, true><<<NBLK, NT, SMEM_SZ>>>(enc, 0, 0, 1);
    for (int it = 1; it <= 8; ++it)
        kmeans_iter<false, false, true><<<NBLK, NT, SMEM_SZ>>>(
            enc, (it - 1) % 3, it % 3, (it + 1) % 3);
    // iter 9: loss only
    kmeans_iter<false, true, false><<<NBLK, NT, SMEM_SZ>>>(enc, 2, 0, 0);

    // join
    cudaStreamWaitEvent(0, evJoin, 0);
    final_kernel<<<1, 1>>>(out);
}